// round 7
// baseline (speedup 1.0000x reference)
#include <cuda_runtime.h>
#include <cuda_bf16.h>

#define H 512
#define W 512
#define OW 510
#define PLANE (H * W)
#define RBLK 2                     // window rows per warp-task
#define PROWS (RBLK + 2)           // pixel rows streamed per task (4)
#define WIN_PER_WARP 30            // 32 lanes -> 30 window cols
#define COLGROUPS 17               // 17 * 30 = 510 exactly
#define ROWGROUPS (OW / RBLK)      // 255 exactly
#define NTASKS (ROWGROUPS * COLGROUPS)   // 4335
#define WARPS_PER_BLOCK 5
#define NBLOCKS (NTASKS / WARPS_PER_BLOCK)   // 867 exactly

__device__ double       g_accum;   // zero-init; restored to 0 each call
__device__ unsigned int g_cnt;     // zero-init; restored to 0 each call

__global__ __launch_bounds__(WARPS_PER_BLOCK * 32)
void ml_fused_kernel(const float* __restrict__ T, const float* __restrict__ V,
                     float* __restrict__ out)
{
    const int warp_id  = threadIdx.x >> 5;
    const int lane     = threadIdx.x & 31;
    const int warp_gid = blockIdx.x * WARPS_PER_BLOCK + warp_id;

    const int rg = warp_gid / COLGROUPS;          // row group 0..254
    const int cg = warp_gid % COLGROUPS;          // col group 0..16
    const int r0 = rg * RBLK;                     // first window row of task
    const int x  = cg * WIN_PER_WARP + lane;      // pixel column 0..511 (always valid)

    float contrib = 0.0f;

    // ring of per-pixel-row stats (22 each), fully unrolled -> registers
    float ring[3][22];

    const float inv9 = 1.0f / 9.0f;
    const float eps9 = 1e-7f * inv9;

    #pragma unroll
    for (int j = 0; j < PROWS; j++) {
        const int base = (r0 + j) * W + x;
        const float t0 = T[0 * PLANE + base];
        const float t1 = T[1 * PLANE + base];
        const float t2 = T[2 * PLANE + base];
        const float v0 = V[0 * PLANE + base];
        const float v1 = V[1 * PLANE + base];
        const float v2 = V[2 * PLANE + base];

        float* rs = ring[j % 3];
        rs[0]  = t0;      rs[1]  = t1;      rs[2]  = t2;
        rs[3]  = v0;      rs[4]  = v1;      rs[5]  = v2;
        rs[6]  = t0 * t0; rs[7]  = t0 * t1; rs[8]  = t0 * t2;
        rs[9]  = t1 * t1; rs[10] = t1 * t2; rs[11] = t2 * t2;
        rs[12] = v0 * v0 + v1 * v1 + v2 * v2;
        rs[13] = t0 * v0; rs[14] = t0 * v1; rs[15] = t0 * v2;
        rs[16] = t1 * v0; rs[17] = t1 * v1; rs[18] = t1 * v2;
        rs[19] = t2 * v0; rs[20] = t2 * v1; rs[21] = t2 * v2;

        if (j >= 2) {
            // column-segment stats = sum of the 3 resident rows
            float cs[22];
            #pragma unroll
            for (int k = 0; k < 22; k++)
                cs[k] = ring[0][k] + ring[1][k] + ring[2][k];

            // horizontal window sum across 3 columns (lane, lane+1, lane+2)
            #pragma unroll
            for (int k = 0; k < 22; k++) {
                const float a = __shfl_down_sync(0xffffffffu, cs[k], 1);
                const float b = __shfl_down_sync(0xffffffffu, cs[k], 2);
                cs[k] += a + b;
            }

            // per-window math (valid for lane < 30)
            const float mu0 = cs[0] * inv9, mu1 = cs[1] * inv9, mu2 = cs[2] * inv9;
            const float sV0 = cs[3], sV1 = cs[4], sV2 = cs[5];

            const float a00 = cs[6]  * inv9 - mu0 * mu0 + eps9;
            const float a01 = cs[7]  * inv9 - mu0 * mu1;
            const float a02 = cs[8]  * inv9 - mu0 * mu2;
            const float a11 = cs[9]  * inv9 - mu1 * mu1 + eps9;
            const float a12 = cs[10] * inv9 - mu1 * mu2;
            const float a22 = cs[11] * inv9 - mu2 * mu2 + eps9;

            const float c00 = a11 * a22 - a12 * a12;
            const float c01 = a02 * a12 - a01 * a22;
            const float c02 = a01 * a12 - a02 * a11;
            const float c11 = a00 * a22 - a02 * a02;
            const float c12 = a01 * a02 - a00 * a12;
            const float c22 = a00 * a11 - a01 * a01;
            const float det = a00 * c00 + a01 * c01 + a02 * c02;
            const float rdet = 1.0f / det;
            const float i00 = c00 * rdet, i01 = c01 * rdet, i02 = c02 * rdet;
            const float i11 = c11 * rdet, i12 = c12 * rdet, i22 = c22 * rdet;

            float pen = sV0 * sV0 + sV1 * sV1 + sV2 * sV2;

            // channel 0
            {
                const float u0 = cs[13] - mu0 * sV0;
                const float u1 = cs[16] - mu1 * sV0;
                const float u2 = cs[19] - mu2 * sV0;
                pen += i00 * u0 * u0 + i11 * u1 * u1 + i22 * u2 * u2
                     + 2.f * (i01 * u0 * u1 + i02 * u0 * u2 + i12 * u1 * u2);
            }
            // channel 1
            {
                const float u0 = cs[14] - mu0 * sV1;
                const float u1 = cs[17] - mu1 * sV1;
                const float u2 = cs[20] - mu2 * sV1;
                pen += i00 * u0 * u0 + i11 * u1 * u1 + i22 * u2 * u2
                     + 2.f * (i01 * u0 * u1 + i02 * u0 * u2 + i12 * u1 * u2);
            }
            // channel 2
            {
                const float u0 = cs[15] - mu0 * sV2;
                const float u1 = cs[18] - mu1 * sV2;
                const float u2 = cs[21] - mu2 * sV2;
                pen += i00 * u0 * u0 + i11 * u1 * u1 + i22 * u2 * u2
                     + 2.f * (i01 * u0 * u1 + i02 * u0 * u2 + i12 * u1 * u2);
            }

            const float wval = cs[12] - inv9 * pen;
            if (lane < WIN_PER_WARP) contrib += wval;
        }
    }

    // warp reduction
    #pragma unroll
    for (int off = 16; off > 0; off >>= 1)
        contrib += __shfl_xor_sync(0xffffffffu, contrib, off);

    __shared__ float wsum[WARPS_PER_BLOCK];
    __shared__ bool  is_last;
    if (lane == 0) wsum[warp_id] = contrib;
    __syncthreads();

    if (threadIdx.x == 0) {
        float s = 0.f;
        #pragma unroll
        for (int i = 0; i < WARPS_PER_BLOCK; i++) s += wsum[i];
        atomicAdd(&g_accum, (double)s);
        __threadfence();
        unsigned int prev = atomicAdd(&g_cnt, 1u);
        is_last = (prev == NBLOCKS - 1);
    }
    __syncthreads();

    if (is_last && threadIdx.x == 0) {
        __threadfence();
        out[0] = (float)g_accum;
        g_accum = 0.0;
        g_cnt   = 0;
    }
}

extern "C" void kernel_launch(void* const* d_in, const int* in_sizes, int n_in,
                              void* d_out, int out_size)
{
    const float* target = (const float*)d_in[0];
    const float* style  = (const float*)d_in[1];
    float* out = (float*)d_out;

    ml_fused_kernel<<<NBLOCKS, WARPS_PER_BLOCK * 32>>>(target, style, out);
}